// round 2
// baseline (speedup 1.0000x reference)
#include <cuda_runtime.h>

#define D 128
#define TILE 32
#define TP 34          // transposed-A smem row pad (floats)
#define WP 132         // weight smem row pad (floats)
#define NTHREADS 256

#define MAX_N 50000
#define MAX_E 800000

// Scratch (static device globals; no allocations allowed)
__device__ float g_P1[(size_t)MAX_N * D];   // X @ msg_w1[0:128]
__device__ float g_P2[(size_t)MAX_N * D];   // X @ msg_w1[128:256]
__device__ float g_H [(size_t)MAX_N * D];   // sum over edges of relu(P1[src]+P2[dst]+b1)
__device__ float g_deg[MAX_N];              // in-degree (float)
__device__ float g_Wp[D * D];               // msg_w2 @ upd_w1[128:256]
__device__ float g_bp[D];                   // msg_b2 @ upd_w1[128:256]

// ---------------------------------------------------------------------------
__global__ void zero_kernel() {
    size_t idx = (size_t)blockIdx.x * blockDim.x + threadIdx.x;
    size_t stride = (size_t)gridDim.x * blockDim.x;
    const float4 z = make_float4(0.f, 0.f, 0.f, 0.f);
    size_t nH = (size_t)MAX_N * D / 4;
    float4* h4 = (float4*)g_H;
    for (size_t i = idx; i < nH; i += stride) h4[i] = z;
    size_t nd = MAX_N / 4;
    float4* d4 = (float4*)g_deg;
    for (size_t i = idx; i < nd; i += stride) d4[i] = z;
}

// ---------------------------------------------------------------------------
// W' = msg_w2 @ upd_w1_bot  and  b' = msg_b2 @ upd_w1_bot   (tiny, per launch)
__global__ void wprime_kernel(const float* __restrict__ w2,
                              const float* __restrict__ uw1,
                              const float* __restrict__ b2) {
    int idx = blockIdx.x * 256 + threadIdx.x;
    if (blockIdx.x < 64) {
        int k = idx >> 7;
        int c = idx & 127;
        float s = 0.f;
        #pragma unroll 8
        for (int j = 0; j < D; ++j)
            s += __ldg(w2 + k * D + j) * __ldg(uw1 + (size_t)(D + j) * D + c);
        g_Wp[k * D + c] = s;
    } else if (threadIdx.x < D) {
        int c = threadIdx.x;
        float s = 0.f;
        #pragma unroll 8
        for (int j = 0; j < D; ++j)
            s += __ldg(b2 + j) * __ldg(uw1 + (size_t)(D + j) * D + c);
        g_bp[c] = s;
    }
}

// ---------------------------------------------------------------------------
__device__ __forceinline__ void fma8(float* acc, float a, float4 b0, float4 b1) {
    acc[0] += a * b0.x; acc[1] += a * b0.y; acc[2] += a * b0.z; acc[3] += a * b0.w;
    acc[4] += a * b1.x; acc[5] += a * b1.y; acc[6] += a * b1.z; acc[7] += a * b1.w;
}

// Shared GEMM phase: acc[2][8] += A_tile(32 rows, transposed in smem) @ W(128x128 in gmem)
// Thread map: c0 = (tid>>4)*8 cols, r0 = (tid&15)*2 rows.
__device__ __forceinline__ void gemm_phase(const float* __restrict__ gw,
                                           const float* s_aT, float* s_w,
                                           float acc[2][8], int c0, int r0, int tid) {
    for (int kc = 0; kc < D; kc += 64) {
        for (int i = tid; i < 64 * (D / 4); i += NTHREADS) {
            int r = i >> 5, c4 = i & 31;
            *(float4*)(s_w + r * WP + c4 * 4) =
                __ldg((const float4*)(gw + (size_t)(kc + r) * D) + c4);
        }
        __syncthreads();
        const float* aT = s_aT + kc * TP + r0;
        #pragma unroll 8
        for (int k = 0; k < 64; ++k) {
            float2 a = *(const float2*)(aT + k * TP);
            const float* wrow = s_w + k * WP + c0;
            float4 b0 = *(const float4*)(wrow);
            float4 b1 = *(const float4*)(wrow + 4);
            fma8(acc[0], a.x, b0, b1);
            fma8(acc[1], a.y, b0, b1);
        }
        __syncthreads();
    }
}

// ---------------------------------------------------------------------------
// K1: P1 = X @ w1[0:128], P2 = X @ w1[128:256]   (per 32-node tile)
__global__ __launch_bounds__(NTHREADS)
void precompute_kernel(const float* __restrict__ x, const float* __restrict__ w1, int N) {
    extern __shared__ float sm[];
    float* s_aT = sm;                // D*TP
    float* s_wA = sm + D * TP;       // 64*WP
    float* s_wB = s_wA + 64 * WP;    // 64*WP
    const int tid = threadIdx.x;
    const int n0 = blockIdx.x * TILE;

    for (int i = tid; i < TILE * (D / 4); i += NTHREADS) {
        int r = i >> 5, c4 = i & 31;
        int n = n0 + r;
        float4 v = make_float4(0.f, 0.f, 0.f, 0.f);
        if (n < N) v = __ldg((const float4*)(x + (size_t)n * D) + c4);
        int k = c4 * 4;
        s_aT[(k + 0) * TP + r] = v.x;
        s_aT[(k + 1) * TP + r] = v.y;
        s_aT[(k + 2) * TP + r] = v.z;
        s_aT[(k + 3) * TP + r] = v.w;
    }
    __syncthreads();

    const int c0 = (tid >> 4) * 8;
    const int r0 = (tid & 15) * 2;
    float acc1[2][8], acc2[2][8];
    #pragma unroll
    for (int rr = 0; rr < 2; ++rr)
        #pragma unroll
        for (int j = 0; j < 8; ++j) { acc1[rr][j] = 0.f; acc2[rr][j] = 0.f; }

    for (int kc = 0; kc < D; kc += 64) {
        for (int i = tid; i < 64 * (D / 4); i += NTHREADS) {
            int r = i >> 5, c4 = i & 31;
            *(float4*)(s_wA + r * WP + c4 * 4) =
                __ldg((const float4*)(w1 + (size_t)(kc + r) * D) + c4);
            *(float4*)(s_wB + r * WP + c4 * 4) =
                __ldg((const float4*)(w1 + (size_t)(D + kc + r) * D) + c4);
        }
        __syncthreads();
        const float* aT = s_aT + kc * TP + r0;
        #pragma unroll 8
        for (int k = 0; k < 64; ++k) {
            float2 a = *(const float2*)(aT + k * TP);
            const float* wa = s_wA + k * WP + c0;
            const float* wb = s_wB + k * WP + c0;
            float4 a0 = *(const float4*)(wa);
            float4 a1 = *(const float4*)(wa + 4);
            float4 b0 = *(const float4*)(wb);
            float4 b1 = *(const float4*)(wb + 4);
            fma8(acc1[0], a.x, a0, a1);
            fma8(acc1[1], a.y, a0, a1);
            fma8(acc2[0], a.x, b0, b1);
            fma8(acc2[1], a.y, b0, b1);
        }
        __syncthreads();
    }

    #pragma unroll
    for (int rr = 0; rr < 2; ++rr) {
        int n = n0 + r0 + rr;
        if (n < N) {
            float4 o0 = make_float4(acc1[rr][0], acc1[rr][1], acc1[rr][2], acc1[rr][3]);
            float4 o1 = make_float4(acc1[rr][4], acc1[rr][5], acc1[rr][6], acc1[rr][7]);
            *(float4*)(g_P1 + (size_t)n * D + c0)     = o0;
            *(float4*)(g_P1 + (size_t)n * D + c0 + 4) = o1;
            float4 p0 = make_float4(acc2[rr][0], acc2[rr][1], acc2[rr][2], acc2[rr][3]);
            float4 p1 = make_float4(acc2[rr][4], acc2[rr][5], acc2[rr][6], acc2[rr][7]);
            *(float4*)(g_P2 + (size_t)n * D + c0)     = p0;
            *(float4*)(g_P2 + (size_t)n * D + c0 + 4) = p1;
        }
    }
}

// ---------------------------------------------------------------------------
// K2: edge pass. One warp per edge: H[dst] += relu(P1[src]+P2[dst]+b1); deg[dst]++
// NOTE: harness delivers edge_indices as int32 (int64 inputs are downcast).
__global__ __launch_bounds__(256)
void edge_kernel(const int* __restrict__ ei, const float* __restrict__ b1, int E) {
    int w = (int)(((size_t)blockIdx.x * blockDim.x + threadIdx.x) >> 5);
    int lane = threadIdx.x & 31;
    if (w >= E) return;
    int s = __ldg(ei + 2 * (size_t)w);
    int d = __ldg(ei + 2 * (size_t)w + 1);
    float4 p1 = __ldg((const float4*)(g_P1 + (size_t)s * D) + lane);
    float4 p2 = __ldg((const float4*)(g_P2 + (size_t)d * D) + lane);
    float4 bb = __ldg((const float4*)b1 + lane);
    float t0 = fmaxf(p1.x + p2.x + bb.x, 0.f);
    float t1 = fmaxf(p1.y + p2.y + bb.y, 0.f);
    float t2 = fmaxf(p1.z + p2.z + bb.z, 0.f);
    float t3 = fmaxf(p1.w + p2.w + bb.w, 0.f);
    float* h = g_H + (size_t)d * D + lane * 4;
    atomicAdd(h + 0, t0);
    atomicAdd(h + 1, t1);
    atomicAdd(h + 2, t2);
    atomicAdd(h + 3, t3);
    if (lane == 0) atomicAdd(g_deg + d, 1.0f);
}

// ---------------------------------------------------------------------------
// K3: out = relu(X@uw1_top + H@W' + deg*b' + ub1) @ uw2 + ub2
__global__ __launch_bounds__(NTHREADS)
void node_kernel(const float* __restrict__ x,
                 const float* __restrict__ uw1, const float* __restrict__ ub1,
                 const float* __restrict__ uw2, const float* __restrict__ ub2,
                 float* __restrict__ out, int N) {
    extern __shared__ float sm[];
    float* s_xT = sm;                 // D*TP (later reused for relu'd hidden uT)
    float* s_hT = sm + D * TP;        // D*TP
    float* s_w  = sm + 2 * D * TP;    // 64*WP
    const int tid = threadIdx.x;
    const int n0 = blockIdx.x * TILE;

    for (int i = tid; i < TILE * (D / 4); i += NTHREADS) {
        int r = i >> 5, c4 = i & 31;
        int n = n0 + r;
        float4 vx = make_float4(0.f, 0.f, 0.f, 0.f);
        float4 vh = vx;
        if (n < N) {
            vx = __ldg((const float4*)(x + (size_t)n * D) + c4);
            vh = __ldg((const float4*)(g_H + (size_t)n * D) + c4);
        }
        int k = c4 * 4;
        s_xT[(k + 0) * TP + r] = vx.x; s_xT[(k + 1) * TP + r] = vx.y;
        s_xT[(k + 2) * TP + r] = vx.z; s_xT[(k + 3) * TP + r] = vx.w;
        s_hT[(k + 0) * TP + r] = vh.x; s_hT[(k + 1) * TP + r] = vh.y;
        s_hT[(k + 2) * TP + r] = vh.z; s_hT[(k + 3) * TP + r] = vh.w;
    }
    __syncthreads();

    const int c0 = (tid >> 4) * 8;
    const int r0 = (tid & 15) * 2;
    float acc[2][8];
    #pragma unroll
    for (int rr = 0; rr < 2; ++rr)
        #pragma unroll
        for (int j = 0; j < 8; ++j) acc[rr][j] = 0.f;

    gemm_phase(uw1,  s_xT, s_w, acc, c0, r0, tid);   // X @ uw1_top (rows 0..127)
    gemm_phase(g_Wp, s_hT, s_w, acc, c0, r0, tid);   // H @ W'

    // bias + relu, store hidden (transposed) into s_xT (phase-A reads long done)
    float degv[2];
    #pragma unroll
    for (int rr = 0; rr < 2; ++rr) {
        int n = n0 + r0 + rr;
        degv[rr] = (n < N) ? __ldg(g_deg + n) : 0.f;
    }
    #pragma unroll
    for (int j = 0; j < 8; ++j) {
        float bpj = g_bp[c0 + j];
        float b1j = __ldg(ub1 + c0 + j);
        #pragma unroll
        for (int rr = 0; rr < 2; ++rr) {
            float v = acc[rr][j] + degv[rr] * bpj + b1j;
            s_xT[(c0 + j) * TP + r0 + rr] = fmaxf(v, 0.f);
        }
    }
    // gemm_phase's internal __syncthreads after the s_w chunk load also
    // guarantees the uT stores above are visible before any thread reads them.
    float acc2[2][8];
    #pragma unroll
    for (int rr = 0; rr < 2; ++rr)
        #pragma unroll
        for (int j = 0; j < 8; ++j) acc2[rr][j] = 0.f;

    gemm_phase(uw2, s_xT, s_w, acc2, c0, r0, tid);   // hidden @ uw2

    #pragma unroll
    for (int rr = 0; rr < 2; ++rr) {
        int n = n0 + r0 + rr;
        if (n < N) {
            float4 o0 = make_float4(acc2[rr][0] + __ldg(ub2 + c0 + 0),
                                    acc2[rr][1] + __ldg(ub2 + c0 + 1),
                                    acc2[rr][2] + __ldg(ub2 + c0 + 2),
                                    acc2[rr][3] + __ldg(ub2 + c0 + 3));
            float4 o1 = make_float4(acc2[rr][4] + __ldg(ub2 + c0 + 4),
                                    acc2[rr][5] + __ldg(ub2 + c0 + 5),
                                    acc2[rr][6] + __ldg(ub2 + c0 + 6),
                                    acc2[rr][7] + __ldg(ub2 + c0 + 7));
            *(float4*)(out + (size_t)n * D + c0)     = o0;
            *(float4*)(out + (size_t)n * D + c0 + 4) = o1;
        }
    }
}

// ---------------------------------------------------------------------------
extern "C" void kernel_launch(void* const* d_in, const int* in_sizes, int n_in,
                              void* d_out, int out_size) {
    const float* x   = (const float*)d_in[0];
    const int*   ei  = (const int*)d_in[1];     // int64 downcast to int32 by harness
    const float* mw1 = (const float*)d_in[2];
    const float* mb1 = (const float*)d_in[3];
    const float* mw2 = (const float*)d_in[4];
    const float* mb2 = (const float*)d_in[5];
    const float* uw1 = (const float*)d_in[6];
    const float* ub1 = (const float*)d_in[7];
    const float* uw2 = (const float*)d_in[8];
    const float* ub2 = (const float*)d_in[9];
    float* out = (float*)d_out;

    int N = in_sizes[0] / D;
    int E = in_sizes[1] / 2;

    const int SMEM_K1 = (D * TP + 2 * 64 * WP) * 4;   // 84992 B
    const int SMEM_K3 = (2 * D * TP + 64 * WP) * 4;   // 68608 B
    cudaFuncSetAttribute(precompute_kernel, cudaFuncAttributeMaxDynamicSharedMemorySize, SMEM_K1);
    cudaFuncSetAttribute(node_kernel,       cudaFuncAttributeMaxDynamicSharedMemorySize, SMEM_K3);

    zero_kernel<<<4096, 256>>>();
    wprime_kernel<<<65, 256>>>(mw2, uw1, mb2);

    int nblk = (N + TILE - 1) / TILE;
    precompute_kernel<<<nblk, NTHREADS, SMEM_K1>>>(x, mw1, N);

    int eblk = (E + 7) / 8;                // one warp per edge, 8 edges/block
    edge_kernel<<<eblk, 256>>>(ei, mb1, E);

    node_kernel<<<nblk, NTHREADS, SMEM_K3>>>(x, uw1, ub1, uw2, ub2, out, N);
}

// round 3
// speedup vs baseline: 1.2670x; 1.2670x over previous
#include <cuda_runtime.h>

#define D 128
#define TILE 32
#define TP 34          // transposed-A smem row pad (floats)
#define WP 132         // weight smem row pad (floats)
#define NTHREADS 256

#define MAX_N 50000
#define MAX_E 800000

// Scratch (static device globals; no allocations allowed)
__device__ float g_P1[(size_t)MAX_N * D];   // X @ msg_w1[0:128]
__device__ float g_P2[(size_t)MAX_N * D];   // X @ msg_w1[128:256] + msg_b1 (bias folded)
__device__ float g_H [(size_t)MAX_N * D];   // per-dst sum of relu(P1[src]+P2'[dst])
__device__ float g_deg[MAX_N];              // in-degree (float)
__device__ float g_Wp[D * D];               // msg_w2 @ upd_w1[128:256]
__device__ float g_bp[D];                   // msg_b2 @ upd_w1[128:256]

// CSR scratch
__device__ int g_cnt[MAX_N];
__device__ int g_off[MAX_N + 1];
__device__ int g_cur[MAX_N];
__device__ int g_esrc[MAX_E];

// ---------------------------------------------------------------------------
__global__ void zero_cnt_kernel(int N) {
    int i = blockIdx.x * blockDim.x + threadIdx.x;
    if (i < N) g_cnt[i] = 0;
}

// ---------------------------------------------------------------------------
// W' = msg_w2 @ upd_w1_bot  and  b' = msg_b2 @ upd_w1_bot   (tiny, per launch)
__global__ void wprime_kernel(const float* __restrict__ w2,
                              const float* __restrict__ uw1,
                              const float* __restrict__ b2) {
    int idx = blockIdx.x * 256 + threadIdx.x;
    if (blockIdx.x < 64) {
        int k = idx >> 7;
        int c = idx & 127;
        float s = 0.f;
        #pragma unroll 8
        for (int j = 0; j < D; ++j)
            s += __ldg(w2 + k * D + j) * __ldg(uw1 + (size_t)(D + j) * D + c);
        g_Wp[k * D + c] = s;
    } else if (threadIdx.x < D) {
        int c = threadIdx.x;
        float s = 0.f;
        #pragma unroll 8
        for (int j = 0; j < D; ++j)
            s += __ldg(b2 + j) * __ldg(uw1 + (size_t)(D + j) * D + c);
        g_bp[c] = s;
    }
}

// ---------------------------------------------------------------------------
// CSR build: histogram -> scan -> scatter
__global__ void hist_kernel(const int* __restrict__ ei, int E) {
    int i = blockIdx.x * blockDim.x + threadIdx.x;
    if (i < E) {
        int2 e = __ldg((const int2*)ei + i);
        atomicAdd(&g_cnt[e.y], 1);
    }
}

__global__ __launch_bounds__(1024) void scan_kernel(int N, int E) {
    __shared__ int part[1024];
    int t = threadIdx.x;
    int chunk = (N + 1023) >> 10;
    int beg = t * chunk;
    int end = beg + chunk; if (end > N) end = N;
    int s = 0;
    for (int i = beg; i < end; ++i) s += g_cnt[i];
    part[t] = s;
    __syncthreads();
    // Hillis-Steele inclusive scan over the 1024 partials
    for (int off = 1; off < 1024; off <<= 1) {
        int v = (t >= off) ? part[t - off] : 0;
        __syncthreads();
        part[t] += v;
        __syncthreads();
    }
    int run = (t == 0) ? 0 : part[t - 1];
    for (int i = beg; i < end; ++i) {
        g_off[i] = run;
        g_cur[i] = run;
        run += g_cnt[i];
    }
    if (t == 0) g_off[N] = E;
}

__global__ void scatter_kernel(const int* __restrict__ ei, int E) {
    int i = blockIdx.x * blockDim.x + threadIdx.x;
    if (i < E) {
        int2 e = __ldg((const int2*)ei + i);
        int pos = atomicAdd(&g_cur[e.y], 1);
        g_esrc[pos] = e.x;
    }
}

// ---------------------------------------------------------------------------
// Gather: one warp per dst node. H[d] = sum_e relu(P1[src_e] + P2'[d]); no atomics.
__global__ __launch_bounds__(256)
void gather_kernel(int N) {
    int d = (int)((blockIdx.x * 256 + threadIdx.x) >> 5);
    int lane = threadIdx.x & 31;
    if (d >= N) return;
    int beg = __ldg(&g_off[d]);
    int end = __ldg(&g_off[d + 1]);
    float4 p2 = __ldg((const float4*)(g_P2 + (size_t)d * D) + lane);  // b1 folded in
    float4 acc = make_float4(0.f, 0.f, 0.f, 0.f);
    int j = beg;
    for (; j + 1 < end; j += 2) {
        int s0 = __ldg(g_esrc + j);
        int s1 = __ldg(g_esrc + j + 1);
        float4 a = __ldg((const float4*)(g_P1 + (size_t)s0 * D) + lane);
        float4 b = __ldg((const float4*)(g_P1 + (size_t)s1 * D) + lane);
        acc.x += fmaxf(a.x + p2.x, 0.f) + fmaxf(b.x + p2.x, 0.f);
        acc.y += fmaxf(a.y + p2.y, 0.f) + fmaxf(b.y + p2.y, 0.f);
        acc.z += fmaxf(a.z + p2.z, 0.f) + fmaxf(b.z + p2.z, 0.f);
        acc.w += fmaxf(a.w + p2.w, 0.f) + fmaxf(b.w + p2.w, 0.f);
    }
    if (j < end) {
        int s0 = __ldg(g_esrc + j);
        float4 a = __ldg((const float4*)(g_P1 + (size_t)s0 * D) + lane);
        acc.x += fmaxf(a.x + p2.x, 0.f);
        acc.y += fmaxf(a.y + p2.y, 0.f);
        acc.z += fmaxf(a.z + p2.z, 0.f);
        acc.w += fmaxf(a.w + p2.w, 0.f);
    }
    *((float4*)(g_H + (size_t)d * D) + lane) = acc;
    if (lane == 0) g_deg[d] = (float)(end - beg);
}

// ---------------------------------------------------------------------------
__device__ __forceinline__ void fma8(float* acc, float a, float4 b0, float4 b1) {
    acc[0] += a * b0.x; acc[1] += a * b0.y; acc[2] += a * b0.z; acc[3] += a * b0.w;
    acc[4] += a * b1.x; acc[5] += a * b1.y; acc[6] += a * b1.z; acc[7] += a * b1.w;
}

// Shared GEMM phase: acc[2][8] += A_tile(32 rows, transposed in smem) @ W(128x128 in gmem)
__device__ __forceinline__ void gemm_phase(const float* __restrict__ gw,
                                           const float* s_aT, float* s_w,
                                           float acc[2][8], int c0, int r0, int tid) {
    for (int kc = 0; kc < D; kc += 64) {
        for (int i = tid; i < 64 * (D / 4); i += NTHREADS) {
            int r = i >> 5, c4 = i & 31;
            *(float4*)(s_w + r * WP + c4 * 4) =
                __ldg((const float4*)(gw + (size_t)(kc + r) * D) + c4);
        }
        __syncthreads();
        const float* aT = s_aT + kc * TP + r0;
        #pragma unroll 8
        for (int k = 0; k < 64; ++k) {
            float2 a = *(const float2*)(aT + k * TP);
            const float* wrow = s_w + k * WP + c0;
            float4 b0 = *(const float4*)(wrow);
            float4 b1 = *(const float4*)(wrow + 4);
            fma8(acc[0], a.x, b0, b1);
            fma8(acc[1], a.y, b0, b1);
        }
        __syncthreads();
    }
}

// ---------------------------------------------------------------------------
// K1: P1 = X @ w1[0:128], P2 = X @ w1[128:256] + b1
__global__ __launch_bounds__(NTHREADS)
void precompute_kernel(const float* __restrict__ x, const float* __restrict__ w1,
                       const float* __restrict__ b1, int N) {
    extern __shared__ float sm[];
    float* s_aT = sm;                // D*TP
    float* s_wA = sm + D * TP;       // 64*WP
    float* s_wB = s_wA + 64 * WP;    // 64*WP
    const int tid = threadIdx.x;
    const int n0 = blockIdx.x * TILE;

    for (int i = tid; i < TILE * (D / 4); i += NTHREADS) {
        int r = i >> 5, c4 = i & 31;
        int n = n0 + r;
        float4 v = make_float4(0.f, 0.f, 0.f, 0.f);
        if (n < N) v = __ldg((const float4*)(x + (size_t)n * D) + c4);
        int k = c4 * 4;
        s_aT[(k + 0) * TP + r] = v.x;
        s_aT[(k + 1) * TP + r] = v.y;
        s_aT[(k + 2) * TP + r] = v.z;
        s_aT[(k + 3) * TP + r] = v.w;
    }
    __syncthreads();

    const int c0 = (tid >> 4) * 8;
    const int r0 = (tid & 15) * 2;
    float acc1[2][8], acc2[2][8];
    #pragma unroll
    for (int rr = 0; rr < 2; ++rr)
        #pragma unroll
        for (int j = 0; j < 8; ++j) { acc1[rr][j] = 0.f; acc2[rr][j] = 0.f; }

    for (int kc = 0; kc < D; kc += 64) {
        for (int i = tid; i < 64 * (D / 4); i += NTHREADS) {
            int r = i >> 5, c4 = i & 31;
            *(float4*)(s_wA + r * WP + c4 * 4) =
                __ldg((const float4*)(w1 + (size_t)(kc + r) * D) + c4);
            *(float4*)(s_wB + r * WP + c4 * 4) =
                __ldg((const float4*)(w1 + (size_t)(D + kc + r) * D) + c4);
        }
        __syncthreads();
        const float* aT = s_aT + kc * TP + r0;
        #pragma unroll 8
        for (int k = 0; k < 64; ++k) {
            float2 a = *(const float2*)(aT + k * TP);
            const float* wa = s_wA + k * WP + c0;
            const float* wb = s_wB + k * WP + c0;
            float4 a0 = *(const float4*)(wa);
            float4 a1 = *(const float4*)(wa + 4);
            float4 b0 = *(const float4*)(wb);
            float4 b1 = *(const float4*)(wb + 4);
            fma8(acc1[0], a.x, a0, a1);
            fma8(acc1[1], a.y, a0, a1);
            fma8(acc2[0], a.x, b0, b1);
            fma8(acc2[1], a.y, b0, b1);
        }
        __syncthreads();
    }

    float4 bb0 = __ldg((const float4*)(b1 + c0));
    float4 bb1 = __ldg((const float4*)(b1 + c0 + 4));
    #pragma unroll
    for (int rr = 0; rr < 2; ++rr) {
        int n = n0 + r0 + rr;
        if (n < N) {
            float4 o0 = make_float4(acc1[rr][0], acc1[rr][1], acc1[rr][2], acc1[rr][3]);
            float4 o1 = make_float4(acc1[rr][4], acc1[rr][5], acc1[rr][6], acc1[rr][7]);
            *(float4*)(g_P1 + (size_t)n * D + c0)     = o0;
            *(float4*)(g_P1 + (size_t)n * D + c0 + 4) = o1;
            float4 p0 = make_float4(acc2[rr][0] + bb0.x, acc2[rr][1] + bb0.y,
                                    acc2[rr][2] + bb0.z, acc2[rr][3] + bb0.w);
            float4 p1 = make_float4(acc2[rr][4] + bb1.x, acc2[rr][5] + bb1.y,
                                    acc2[rr][6] + bb1.z, acc2[rr][7] + bb1.w);
            *(float4*)(g_P2 + (size_t)n * D + c0)     = p0;
            *(float4*)(g_P2 + (size_t)n * D + c0 + 4) = p1;
        }
    }
}

// ---------------------------------------------------------------------------
// K3: out = relu(X@uw1_top + H@W' + deg*b' + ub1) @ uw2 + ub2
__global__ __launch_bounds__(NTHREADS)
void node_kernel(const float* __restrict__ x,
                 const float* __restrict__ uw1, const float* __restrict__ ub1,
                 const float* __restrict__ uw2, const float* __restrict__ ub2,
                 float* __restrict__ out, int N) {
    extern __shared__ float sm[];
    float* s_xT = sm;                 // D*TP (later reused for relu'd hidden uT)
    float* s_hT = sm + D * TP;        // D*TP
    float* s_w  = sm + 2 * D * TP;    // 64*WP
    const int tid = threadIdx.x;
    const int n0 = blockIdx.x * TILE;

    for (int i = tid; i < TILE * (D / 4); i += NTHREADS) {
        int r = i >> 5, c4 = i & 31;
        int n = n0 + r;
        float4 vx = make_float4(0.f, 0.f, 0.f, 0.f);
        float4 vh = vx;
        if (n < N) {
            vx = __ldg((const float4*)(x + (size_t)n * D) + c4);
            vh = __ldg((const float4*)(g_H + (size_t)n * D) + c4);
        }
        int k = c4 * 4;
        s_xT[(k + 0) * TP + r] = vx.x; s_xT[(k + 1) * TP + r] = vx.y;
        s_xT[(k + 2) * TP + r] = vx.z; s_xT[(k + 3) * TP + r] = vx.w;
        s_hT[(k + 0) * TP + r] = vh.x; s_hT[(k + 1) * TP + r] = vh.y;
        s_hT[(k + 2) * TP + r] = vh.z; s_hT[(k + 3) * TP + r] = vh.w;
    }
    __syncthreads();

    const int c0 = (tid >> 4) * 8;
    const int r0 = (tid & 15) * 2;
    float acc[2][8];
    #pragma unroll
    for (int rr = 0; rr < 2; ++rr)
        #pragma unroll
        for (int j = 0; j < 8; ++j) acc[rr][j] = 0.f;

    gemm_phase(uw1,  s_xT, s_w, acc, c0, r0, tid);   // X @ uw1_top (rows 0..127)
    gemm_phase(g_Wp, s_hT, s_w, acc, c0, r0, tid);   // H @ W'

    float degv[2];
    #pragma unroll
    for (int rr = 0; rr < 2; ++rr) {
        int n = n0 + r0 + rr;
        degv[rr] = (n < N) ? __ldg(g_deg + n) : 0.f;
    }
    #pragma unroll
    for (int j = 0; j < 8; ++j) {
        float bpj = g_bp[c0 + j];
        float b1j = __ldg(ub1 + c0 + j);
        #pragma unroll
        for (int rr = 0; rr < 2; ++rr) {
            float v = acc[rr][j] + degv[rr] * bpj + b1j;
            s_xT[(c0 + j) * TP + r0 + rr] = fmaxf(v, 0.f);
        }
    }
    // gemm_phase's first internal __syncthreads fences the s_xT writes above.
    float acc2[2][8];
    #pragma unroll
    for (int rr = 0; rr < 2; ++rr)
        #pragma unroll
        for (int j = 0; j < 8; ++j) acc2[rr][j] = 0.f;

    gemm_phase(uw2, s_xT, s_w, acc2, c0, r0, tid);   // hidden @ uw2

    #pragma unroll
    for (int rr = 0; rr < 2; ++rr) {
        int n = n0 + r0 + rr;
        if (n < N) {
            float4 o0 = make_float4(acc2[rr][0] + __ldg(ub2 + c0 + 0),
                                    acc2[rr][1] + __ldg(ub2 + c0 + 1),
                                    acc2[rr][2] + __ldg(ub2 + c0 + 2),
                                    acc2[rr][3] + __ldg(ub2 + c0 + 3));
            float4 o1 = make_float4(acc2[rr][4] + __ldg(ub2 + c0 + 4),
                                    acc2[rr][5] + __ldg(ub2 + c0 + 5),
                                    acc2[rr][6] + __ldg(ub2 + c0 + 6),
                                    acc2[rr][7] + __ldg(ub2 + c0 + 7));
            *(float4*)(out + (size_t)n * D + c0)     = o0;
            *(float4*)(out + (size_t)n * D + c0 + 4) = o1;
        }
    }
}

// ---------------------------------------------------------------------------
extern "C" void kernel_launch(void* const* d_in, const int* in_sizes, int n_in,
                              void* d_out, int out_size) {
    const float* x   = (const float*)d_in[0];
    const int*   ei  = (const int*)d_in[1];     // int64 downcast to int32 by harness
    const float* mw1 = (const float*)d_in[2];
    const float* mb1 = (const float*)d_in[3];
    const float* mw2 = (const float*)d_in[4];
    const float* mb2 = (const float*)d_in[5];
    const float* uw1 = (const float*)d_in[6];
    const float* ub1 = (const float*)d_in[7];
    const float* uw2 = (const float*)d_in[8];
    const float* ub2 = (const float*)d_in[9];
    float* out = (float*)d_out;

    int N = in_sizes[0] / D;
    int E = in_sizes[1] / 2;

    const int SMEM_K1 = (D * TP + 2 * 64 * WP) * 4;   // 84992 B
    const int SMEM_K3 = (2 * D * TP + 64 * WP) * 4;   // 68608 B
    cudaFuncSetAttribute(precompute_kernel, cudaFuncAttributeMaxDynamicSharedMemorySize, SMEM_K1);
    cudaFuncSetAttribute(node_kernel,       cudaFuncAttributeMaxDynamicSharedMemorySize, SMEM_K3);

    zero_cnt_kernel<<<(N + 255) / 256, 256>>>(N);
    wprime_kernel<<<65, 256>>>(mw2, uw1, mb2);

    int nblk = (N + TILE - 1) / TILE;
    precompute_kernel<<<nblk, NTHREADS, SMEM_K1>>>(x, mw1, mb1, N);

    int eblk = (E + 255) / 256;
    hist_kernel<<<eblk, 256>>>(ei, E);
    scan_kernel<<<1, 1024>>>(N, E);
    scatter_kernel<<<eblk, 256>>>(ei, E);
    gather_kernel<<<(N * 32 + 255) / 256, 256>>>(N);

    node_kernel<<<nblk, NTHREADS, SMEM_K3>>>(x, uw1, ub1, uw2, ub2, out, N);
}

// round 5
// speedup vs baseline: 1.8125x; 1.4306x over previous
#include <cuda_runtime.h>
#include <cuda_bf16.h>
#include <cstdint>

#define D 128
#define NTHREADS 256
#define PA 68           // A-tile pair-word row pitch (kp dim 64) ; 68 % 32 == 4 -> conflict-free frags
#define PB 136          // B-tile pair-word row pitch (n dim 128) ; 136 % 32 == 8 -> conflict-free frags

#define MAX_N 50000
#define MAX_E 800000

// Scratch (static device globals; no allocations allowed)
__device__ float g_P1[(size_t)MAX_N * D];   // X @ msg_w1[0:128]
__device__ float g_P2[(size_t)MAX_N * D];   // X @ msg_w1[128:256] + msg_b1
__device__ float g_H [(size_t)MAX_N * D];   // per-dst sum of relu(P1[src]+P2'[dst])
__device__ float g_deg[MAX_N];              // in-degree (float)
__device__ float g_Wp[D * D];               // msg_w2 @ upd_w1[128:256]
__device__ float g_bp[D];                   // msg_b2 @ upd_w1[128:256]

// CSR scratch
__device__ int g_cnt[MAX_N];
__device__ int g_off[MAX_N + 1];
__device__ int g_cur[MAX_N];
__device__ int g_esrc[MAX_E];

// ---------------------------------------------------------------------------
__global__ void zero_cnt_kernel(int N) {
    int i = blockIdx.x * blockDim.x + threadIdx.x;
    if (i < N) g_cnt[i] = 0;
}

// ---------------------------------------------------------------------------
// W' = msg_w2 @ upd_w1_bot  and  b' = msg_b2 @ upd_w1_bot   (tiny, per launch)
__global__ void wprime_kernel(const float* __restrict__ w2,
                              const float* __restrict__ uw1,
                              const float* __restrict__ b2) {
    int idx = blockIdx.x * 256 + threadIdx.x;
    if (blockIdx.x < 64) {
        int k = idx >> 7;
        int c = idx & 127;
        float s = 0.f;
        #pragma unroll 8
        for (int j = 0; j < D; ++j)
            s += __ldg(w2 + k * D + j) * __ldg(uw1 + (size_t)(D + j) * D + c);
        g_Wp[k * D + c] = s;
    } else if (threadIdx.x < D) {
        int c = threadIdx.x;
        float s = 0.f;
        #pragma unroll 8
        for (int j = 0; j < D; ++j)
            s += __ldg(b2 + j) * __ldg(uw1 + (size_t)(D + j) * D + c);
        g_bp[c] = s;
    }
}

// ---------------------------------------------------------------------------
// CSR build: histogram -> scan -> scatter
__global__ void hist_kernel(const int* __restrict__ ei, int E) {
    int i = blockIdx.x * blockDim.x + threadIdx.x;
    if (i < E) {
        int2 e = __ldg((const int2*)ei + i);
        atomicAdd(&g_cnt[e.y], 1);
    }
}

__global__ __launch_bounds__(1024) void scan_kernel(int N, int E) {
    __shared__ int part[1024];
    int t = threadIdx.x;
    int chunk = (N + 1023) >> 10;
    int beg = t * chunk;
    int end = beg + chunk; if (end > N) end = N;
    int s = 0;
    for (int i = beg; i < end; ++i) s += g_cnt[i];
    part[t] = s;
    __syncthreads();
    for (int off = 1; off < 1024; off <<= 1) {
        int v = (t >= off) ? part[t - off] : 0;
        __syncthreads();
        part[t] += v;
        __syncthreads();
    }
    int run = (t == 0) ? 0 : part[t - 1];
    for (int i = beg; i < end; ++i) {
        g_off[i] = run;
        g_cur[i] = run;
        run += g_cnt[i];
    }
    if (t == 0) g_off[N] = E;
}

__global__ void scatter_kernel(const int* __restrict__ ei, int E) {
    int i = blockIdx.x * blockDim.x + threadIdx.x;
    if (i < E) {
        int2 e = __ldg((const int2*)ei + i);
        int pos = atomicAdd(&g_cur[e.y], 1);
        g_esrc[pos] = e.x;
    }
}

// ---------------------------------------------------------------------------
// Gather: one warp per dst node. H[d] = sum_e relu(P1[src_e] + P2'[d]); no atomics.
__global__ __launch_bounds__(256)
void gather_kernel(int N) {
    int d = (int)((blockIdx.x * 256 + threadIdx.x) >> 5);
    int lane = threadIdx.x & 31;
    if (d >= N) return;
    int beg = __ldg(&g_off[d]);
    int end = __ldg(&g_off[d + 1]);
    float4 p2 = __ldg((const float4*)(g_P2 + (size_t)d * D) + lane);
    float4 acc = make_float4(0.f, 0.f, 0.f, 0.f);
    int j = beg;
    for (; j + 1 < end; j += 2) {
        int s0 = __ldg(g_esrc + j);
        int s1 = __ldg(g_esrc + j + 1);
        float4 a = __ldg((const float4*)(g_P1 + (size_t)s0 * D) + lane);
        float4 b = __ldg((const float4*)(g_P1 + (size_t)s1 * D) + lane);
        acc.x += fmaxf(a.x + p2.x, 0.f) + fmaxf(b.x + p2.x, 0.f);
        acc.y += fmaxf(a.y + p2.y, 0.f) + fmaxf(b.y + p2.y, 0.f);
        acc.z += fmaxf(a.z + p2.z, 0.f) + fmaxf(b.z + p2.z, 0.f);
        acc.w += fmaxf(a.w + p2.w, 0.f) + fmaxf(b.w + p2.w, 0.f);
    }
    if (j < end) {
        int s0 = __ldg(g_esrc + j);
        float4 a = __ldg((const float4*)(g_P1 + (size_t)s0 * D) + lane);
        acc.x += fmaxf(a.x + p2.x, 0.f);
        acc.y += fmaxf(a.y + p2.y, 0.f);
        acc.z += fmaxf(a.z + p2.z, 0.f);
        acc.w += fmaxf(a.w + p2.w, 0.f);
    }
    *((float4*)(g_H + (size_t)d * D) + lane) = acc;
    if (lane == 0) g_deg[d] = (float)(end - beg);
}

// ===========================================================================
// bf16x3 tensor-core GEMM machinery
// f32 operand split into hi/lo bf16 planes; acc += Ah*Bh + Al*Bh + Ah*Bl.
// Dropped Al*Bl term ~2^-16 relative per product -> rel_err ~1e-5 (gate 1e-3).
// ===========================================================================

__device__ __forceinline__ void mma16816(float c[4],
                                         uint32_t a0, uint32_t a1, uint32_t a2, uint32_t a3,
                                         uint32_t b0, uint32_t b1) {
    asm volatile(
        "mma.sync.aligned.m16n8k16.row.col.f32.bf16.bf16.f32 "
        "{%0,%1,%2,%3}, {%4,%5,%6,%7}, {%8,%9}, {%0,%1,%2,%3};"
        : "+f"(c[0]), "+f"(c[1]), "+f"(c[2]), "+f"(c[3])
        : "r"(a0), "r"(a1), "r"(a2), "r"(a3), "r"(b0), "r"(b1));
}

// Split (x,y) [k, k+1 adjacent] into hi/lo packed bf16x2 words.
__device__ __forceinline__ void split2(float x, float y, uint32_t& hi, uint32_t& lo) {
    __nv_bfloat162 hp = __floats2bfloat162_rn(x, y);   // .x = x (low half = smaller k)
    float xh = __low2float(hp);
    float yh = __high2float(hp);
    __nv_bfloat162 lp = __floats2bfloat162_rn(x - xh, y - yh);
    hi = *reinterpret_cast<uint32_t*>(&hp);
    lo = *reinterpret_cast<uint32_t*>(&lp);
}

// Fill A tile (128 rows x 64 kp), pre-split, from global f32 [rows][128].
__device__ __forceinline__ void fill_A(uint32_t* sA0, uint32_t* sA1,
                                       const float* __restrict__ src,
                                       int rowBase, int N, int tid) {
    for (int i = tid; i < 128 * 64; i += NTHREADS) {
        int m = i >> 6, kp = i & 63;
        int gm = rowBase + m;
        float2 v = make_float2(0.f, 0.f);
        if (gm < N) v = *(const float2*)(src + (size_t)gm * D + 2 * kp);
        uint32_t h, l;
        split2(v.x, v.y, h, l);
        sA0[m * PA + kp] = h;
        sA1[m * PA + kp] = l;
    }
}

// Fill B chunk (32 kp x 128 n), pre-split, from weight rows w[0..63][128].
__device__ __forceinline__ void fill_B(uint32_t* sB0, uint32_t* sB1,
                                       const float* __restrict__ w, int tid) {
    for (int i = tid; i < 32 * 128; i += NTHREADS) {
        int kp = i >> 7, n = i & 127;
        float x = __ldg(w + (size_t)(2 * kp) * D + n);
        float y = __ldg(w + (size_t)(2 * kp + 1) * D + n);
        uint32_t h, l;
        split2(x, y, h, l);
        sB0[kp * PB + n] = h;
        sB1[kp * PB + n] = l;
    }
}

// One 64-k chunk of mma work. Warp tile: rows [16w,16w+16), all 16 n-tiles.
__device__ __forceinline__ void mma_chunk(const uint32_t* sA0, const uint32_t* sA1,
                                          const uint32_t* sB0, const uint32_t* sB1,
                                          float acc[16][4], int w, int r, int t,
                                          int kpBase) {
    #pragma unroll
    for (int ks = 0; ks < 4; ++ks) {
        int kpA = kpBase + ks * 8;
        const uint32_t* a0p = sA0 + (16 * w + r) * PA + kpA;
        const uint32_t* a1p = sA0 + (16 * w + r + 8) * PA + kpA;
        const uint32_t* l0p = sA1 + (16 * w + r) * PA + kpA;
        const uint32_t* l1p = sA1 + (16 * w + r + 8) * PA + kpA;
        uint32_t ah0 = a0p[t],     ah1 = a1p[t];
        uint32_t ah2 = a0p[4 + t], ah3 = a1p[4 + t];
        uint32_t al0 = l0p[t],     al1 = l1p[t];
        uint32_t al2 = l0p[4 + t], al3 = l1p[4 + t];
        #pragma unroll
        for (int j = 0; j < 16; ++j) {
            int n = 8 * j + r;
            uint32_t bh0 = sB0[(ks * 8 + t) * PB + n];
            uint32_t bh1 = sB0[(ks * 8 + 4 + t) * PB + n];
            uint32_t bl0 = sB1[(ks * 8 + t) * PB + n];
            uint32_t bl1 = sB1[(ks * 8 + 4 + t) * PB + n];
            mma16816(acc[j], ah0, ah1, ah2, ah3, bh0, bh1);
            mma16816(acc[j], al0, al1, al2, al3, bh0, bh1);
            mma16816(acc[j], ah0, ah1, ah2, ah3, bl0, bl1);
        }
    }
}

__device__ __forceinline__ void zero_acc(float acc[16][4]) {
    #pragma unroll
    for (int j = 0; j < 16; ++j)
        #pragma unroll
        for (int q = 0; q < 4; ++q) acc[j][q] = 0.f;
}

// smem word offsets
#define SA0_OFF 0
#define SA1_OFF (128 * PA)
#define SB0_OFF (2 * 128 * PA)
#define SB1_OFF (2 * 128 * PA + 32 * PB)
#define SMEM_MMA_BYTES ((2 * 128 * PA + 2 * 32 * PB) * 4)

// ---------------------------------------------------------------------------
// K1: P1 = X @ w1[0:128], P2 = X @ w1[128:256] + b1   (bf16x3 mma)
__global__ __launch_bounds__(256)
void precompute_mma(const float* __restrict__ x, const float* __restrict__ w1,
                    const float* __restrict__ b1, int N) {
    extern __shared__ uint32_t smu[];
    uint32_t* sA0 = smu + SA0_OFF;
    uint32_t* sA1 = smu + SA1_OFF;
    uint32_t* sB0 = smu + SB0_OFF;
    uint32_t* sB1 = smu + SB1_OFF;
    const int tid = threadIdx.x;
    const int w = tid >> 5, lane = tid & 31, r = lane >> 2, t = lane & 3;
    const int rowBase = blockIdx.x * 128;

    fill_A(sA0, sA1, x, rowBase, N, tid);
    __syncthreads();

    float acc[16][4];
    const int gm0 = rowBase + 16 * w + r;
    const int gm1 = gm0 + 8;

    // ---- P1 = X @ w1[0:128] ----
    zero_acc(acc);
    #pragma unroll
    for (int c = 0; c < 2; ++c) {
        fill_B(sB0, sB1, w1 + (size_t)(c * 64) * D, tid);
        __syncthreads();
        mma_chunk(sA0, sA1, sB0, sB1, acc, w, r, t, c * 32);
        __syncthreads();
    }
    #pragma unroll
    for (int j = 0; j < 16; ++j) {
        int col = 8 * j + 2 * t;
        if (gm0 < N) *(float2*)(g_P1 + (size_t)gm0 * D + col) = make_float2(acc[j][0], acc[j][1]);
        if (gm1 < N) *(float2*)(g_P1 + (size_t)gm1 * D + col) = make_float2(acc[j][2], acc[j][3]);
    }

    // ---- P2 = X @ w1[128:256] + b1 ----
    zero_acc(acc);
    #pragma unroll
    for (int c = 0; c < 2; ++c) {
        fill_B(sB0, sB1, w1 + (size_t)(128 + c * 64) * D, tid);
        __syncthreads();
        mma_chunk(sA0, sA1, sB0, sB1, acc, w, r, t, c * 32);
        __syncthreads();
    }
    #pragma unroll
    for (int j = 0; j < 16; ++j) {
        int col = 8 * j + 2 * t;
        float b0 = __ldg(b1 + col), b2 = __ldg(b1 + col + 1);
        if (gm0 < N) *(float2*)(g_P2 + (size_t)gm0 * D + col) = make_float2(acc[j][0] + b0, acc[j][1] + b2);
        if (gm1 < N) *(float2*)(g_P2 + (size_t)gm1 * D + col) = make_float2(acc[j][2] + b0, acc[j][3] + b2);
    }
}

// ---------------------------------------------------------------------------
// K3: out = relu(X@uw1_top + H@W' + deg*b' + ub1) @ uw2 + ub2   (bf16x3 mma)
__global__ __launch_bounds__(256)
void node_mma(const float* __restrict__ x,
              const float* __restrict__ uw1, const float* __restrict__ ub1,
              const float* __restrict__ uw2, const float* __restrict__ ub2,
              float* __restrict__ out, int N) {
    extern __shared__ uint32_t smu[];
    uint32_t* sA0 = smu + SA0_OFF;
    uint32_t* sA1 = smu + SA1_OFF;
    uint32_t* sB0 = smu + SB0_OFF;
    uint32_t* sB1 = smu + SB1_OFF;
    const int tid = threadIdx.x;
    const int w = tid >> 5, lane = tid & 31, r = lane >> 2, t = lane & 3;
    const int rowBase = blockIdx.x * 128;
    const int gm0 = rowBase + 16 * w + r;
    const int gm1 = gm0 + 8;

    float acc[16][4];
    zero_acc(acc);

    // ---- stage 1a: X @ uw1[0:128] ----
    fill_A(sA0, sA1, x, rowBase, N, tid);
    __syncthreads();
    #pragma unroll
    for (int c = 0; c < 2; ++c) {
        fill_B(sB0, sB1, uw1 + (size_t)(c * 64) * D, tid);
        __syncthreads();
        mma_chunk(sA0, sA1, sB0, sB1, acc, w, r, t, c * 32);
        __syncthreads();
    }

    // ---- stage 1b: + H @ Wp ----
    fill_A(sA0, sA1, g_H, rowBase, N, tid);
    __syncthreads();
    #pragma unroll
    for (int c = 0; c < 2; ++c) {
        fill_B(sB0, sB1, g_Wp + (size_t)(c * 64) * D, tid);
        __syncthreads();
        mma_chunk(sA0, sA1, sB0, sB1, acc, w, r, t, c * 32);
        __syncthreads();
    }

    // ---- epilogue 1: biases + deg*b' + relu ; re-split hidden into sA ----
    {
        float dg0 = (gm0 < N) ? __ldg(g_deg + gm0) : 0.f;
        float dg1 = (gm1 < N) ? __ldg(g_deg + gm1) : 0.f;
        #pragma unroll
        for (int j = 0; j < 16; ++j) {
            int col = 8 * j + 2 * t;
            float bp0 = g_bp[col], bp1 = g_bp[col + 1];
            float u0 = __ldg(ub1 + col), u1 = __ldg(ub1 + col + 1);
            float v00 = fmaxf(acc[j][0] + dg0 * bp0 + u0, 0.f);
            float v01 = fmaxf(acc[j][1] + dg0 * bp1 + u1, 0.f);
            float v10 = fmaxf(acc[j][2] + dg1 * bp0 + u0, 0.f);
            float v11 = fmaxf(acc[j][3] + dg1 * bp1 + u1, 0.f);
            int kp = 4 * j + t;
            uint32_t h, l;
            split2(v00, v01, h, l);
            sA0[(16 * w + r) * PA + kp] = h;
            sA1[(16 * w + r) * PA + kp] = l;
            split2(v10, v11, h, l);
            sA0[(16 * w + r + 8) * PA + kp] = h;
            sA1[(16 * w + r + 8) * PA + kp] = l;
        }
    }
    __syncthreads();

    // ---- stage 2: hidden @ uw2 ----
    zero_acc(acc);
    #pragma unroll
    for (int c = 0; c < 2; ++c) {
        fill_B(sB0, sB1, uw2 + (size_t)(c * 64) * D, tid);
        __syncthreads();
        mma_chunk(sA0, sA1, sB0, sB1, acc, w, r, t, c * 32);
        __syncthreads();
    }

    #pragma unroll
    for (int j = 0; j < 16; ++j) {
        int col = 8 * j + 2 * t;
        float b0 = __ldg(ub2 + col), b2 = __ldg(ub2 + col + 1);
        if (gm0 < N) *(float2*)(out + (size_t)gm0 * D + col) = make_float2(acc[j][0] + b0, acc[j][1] + b2);
        if (gm1 < N) *(float2*)(out + (size_t)gm1 * D + col) = make_float2(acc[j][2] + b0, acc[j][3] + b2);
    }
}

// ---------------------------------------------------------------------------
extern "C" void kernel_launch(void* const* d_in, const int* in_sizes, int n_in,
                              void* d_out, int out_size) {
    const float* x   = (const float*)d_in[0];
    const int*   ei  = (const int*)d_in[1];     // int64 downcast to int32 by harness
    const float* mw1 = (const float*)d_in[2];
    const float* mb1 = (const float*)d_in[3];
    const float* mw2 = (const float*)d_in[4];
    const float* mb2 = (const float*)d_in[5];
    const float* uw1 = (const float*)d_in[6];
    const float* ub1 = (const float*)d_in[7];
    const float* uw2 = (const float*)d_in[8];
    const float* ub2 = (const float*)d_in[9];
    float* out = (float*)d_out;

    int N = in_sizes[0] / D;
    int E = in_sizes[1] / 2;

    cudaFuncSetAttribute(precompute_mma, cudaFuncAttributeMaxDynamicSharedMemorySize, SMEM_MMA_BYTES);
    cudaFuncSetAttribute(node_mma,       cudaFuncAttributeMaxDynamicSharedMemorySize, SMEM_MMA_BYTES);

    zero_cnt_kernel<<<(N + 255) / 256, 256>>>(N);
    wprime_kernel<<<65, 256>>>(mw2, uw1, mb2);

    int nblk = (N + 127) / 128;
    precompute_mma<<<nblk, NTHREADS, SMEM_MMA_BYTES>>>(x, mw1, mb1, N);

    int eblk = (E + 255) / 256;
    hist_kernel<<<eblk, 256>>>(ei, E);
    scan_kernel<<<1, 1024>>>(N, E);
    scatter_kernel<<<eblk, 256>>>(ei, E);
    gather_kernel<<<(N * 32 + 255) / 256, 256>>>(N);

    node_mma<<<nblk, NTHREADS, SMEM_MMA_BYTES>>>(x, uw1, ub1, uw2, ub2, out, N);
}